// round 1
// baseline (speedup 1.0000x reference)
#include <cuda_runtime.h>
#include <cuda_bf16.h>

#define B_ 2
#define S_ 2048
#define D_ 256
#define H_ 8

// Scratch (no allocations allowed -> static device globals)
__device__ float g_Q[(size_t)B_ * H_ * S_ * D_];   // 32 MB
__device__ float g_K[(size_t)B_ * H_ * S_ * D_];   // 32 MB
__device__ float g_V[(size_t)B_ * H_ * S_ * D_];   // 32 MB
__device__ float g_P[(size_t)B_ * H_ * S_ * S_];   // 256 MB (scores -> probs in place)
__device__ float g_O[(size_t)B_ * S_ * H_ * D_];   // 32 MB, laid out [B,S,H,D] for contiguous final GEMM

// ---------------------------------------------------------------------------
// Generic 64x64 tile fp32 GEMM body. BK=16, 256 threads, 4x4 micro-tile.
// TB=false: C[M,N] = A[M,K] * B[K,N]  (both row-major)
// TB=true : C[M,N] = A[M,K] * B[N,K]^T (B row-major over N, K contiguous)
// Tile coords come from blockIdx.x (M) / blockIdx.y (N). K, leading dims runtime.
// ---------------------------------------------------------------------------
template <bool TB>
__device__ __forceinline__ void gemm_body(const float* __restrict__ A,
                                          const float* __restrict__ Bm,
                                          float* __restrict__ C,
                                          int K, int lda, int ldb, int ldc,
                                          float scale)
{
    __shared__ float As[16][68];   // padded to soften transposed-store conflicts
    __shared__ float Bs[16][68];

    const int t  = threadIdx.x;
    const int m0 = blockIdx.x * 64;
    const int n0 = blockIdx.y * 64;
    const int ty = t >> 4;         // 0..15 : row group
    const int tx = t & 15;         // 0..15 : col group
    const int lrow = t >> 2;       // 0..63 : loader row
    const int lk   = (t & 3) * 4;  // 0,4,8,12 : loader k offset

    float acc[4][4] = {};

    for (int k0 = 0; k0 < K; k0 += 16) {
        // A tile: 64 rows x 16 k, coalesced float4 along k, stored transposed
        float4 av = *(const float4*)(A + (size_t)(m0 + lrow) * lda + (k0 + lk));
        As[lk + 0][lrow] = av.x;
        As[lk + 1][lrow] = av.y;
        As[lk + 2][lrow] = av.z;
        As[lk + 3][lrow] = av.w;

        if (TB) {
            // B tile (NT): 64 n-rows x 16 k, same pattern as A
            float4 bv = *(const float4*)(Bm + (size_t)(n0 + lrow) * ldb + (k0 + lk));
            Bs[lk + 0][lrow] = bv.x;
            Bs[lk + 1][lrow] = bv.y;
            Bs[lk + 2][lrow] = bv.z;
            Bs[lk + 3][lrow] = bv.w;
        } else {
            // B tile (NN): 16 k-rows x 64 n, coalesced float4 along n
            const int bk = t >> 4;
            const int bn = (t & 15) * 4;
            float4 bv = *(const float4*)(Bm + (size_t)(k0 + bk) * ldb + (n0 + bn));
            *(float4*)&Bs[bk][bn] = bv;
        }
        __syncthreads();

        #pragma unroll
        for (int kk = 0; kk < 16; kk++) {
            float4 a4 = *(const float4*)&As[kk][ty * 4];
            float4 b4 = *(const float4*)&Bs[kk][tx * 4];
            float ar[4] = {a4.x, a4.y, a4.z, a4.w};
            float br[4] = {b4.x, b4.y, b4.z, b4.w};
            #pragma unroll
            for (int i = 0; i < 4; i++)
                #pragma unroll
                for (int j = 0; j < 4; j++)
                    acc[i][j] += ar[i] * br[j];
        }
        __syncthreads();
    }

    #pragma unroll
    for (int i = 0; i < 4; i++) {
        float* crow = C + (size_t)(m0 + ty * 4 + i) * ldc + n0 + tx * 4;
        #pragma unroll
        for (int j = 0; j < 4; j++) crow[j] = acc[i][j] * scale;
    }
}

// ---------------------------------------------------------------------------
// 1) Q/K/V projections: for each (which, b, h): [S,D] = X_b[S,D] @ W_h[D,D]
// ---------------------------------------------------------------------------
__global__ void proj_kernel(const float* __restrict__ x,
                            const float* __restrict__ wQ,
                            const float* __restrict__ wK,
                            const float* __restrict__ wV)
{
    const int z     = blockIdx.z;          // 0..3*B*H-1
    const int which = z / (B_ * H_);
    const int bh    = z % (B_ * H_);
    const int b     = bh / H_;
    const int h     = bh % H_;

    const float* A = x + (size_t)b * S_ * D_;
    const float* W = (which == 0 ? wQ : which == 1 ? wK : wV) + (size_t)h * D_ * D_;
    float* C = (which == 0 ? g_Q : which == 1 ? g_K : g_V) + (size_t)bh * S_ * D_;

    gemm_body<false>(A, W, C, D_, D_, D_, D_, 1.0f);
}

// ---------------------------------------------------------------------------
// 2) Scores = Q @ K^T * (1/sqrt(D)). Skip tiles strictly above the diagonal;
//    entries j>i inside diagonal tiles are junk (softmax never reads them).
// ---------------------------------------------------------------------------
__global__ void qk_kernel()
{
    if (blockIdx.y > blockIdx.x) return;   // fully above causal diagonal
    const int bh = blockIdx.z;
    const float* A  = g_Q + (size_t)bh * S_ * D_;
    const float* Bm = g_K + (size_t)bh * S_ * D_;
    float* C = g_P + (size_t)bh * S_ * S_;
    gemm_body<true>(A, Bm, C, D_, D_, D_, S_, 0.0625f);  // 1/sqrt(256)
}

// ---------------------------------------------------------------------------
// 3) Causal softmax, one block per row. softmax-then-mask-then-renorm equals
//    softmax over j<=i exactly. Zero-fills j>i so PV can be a dense GEMM.
// ---------------------------------------------------------------------------
__global__ void softmax_kernel()
{
    const int i  = blockIdx.x;
    const int bh = blockIdx.y;
    float* row = g_P + ((size_t)bh * S_ + i) * S_;
    const int len = i + 1;
    const int t = threadIdx.x;
    __shared__ float red[8];

    float m = -3.402823e38f;
    for (int j = t; j < len; j += 256) m = fmaxf(m, row[j]);
    #pragma unroll
    for (int o = 16; o; o >>= 1) m = fmaxf(m, __shfl_xor_sync(0xffffffffu, m, o));
    if ((t & 31) == 0) red[t >> 5] = m;
    __syncthreads();
    m = red[0];
    #pragma unroll
    for (int w = 1; w < 8; w++) m = fmaxf(m, red[w]);
    __syncthreads();

    float s = 0.0f;
    for (int j = t; j < len; j += 256) {
        float e = __expf(row[j] - m);
        row[j] = e;
        s += e;
    }
    #pragma unroll
    for (int o = 16; o; o >>= 1) s += __shfl_xor_sync(0xffffffffu, s, o);
    if ((t & 31) == 0) red[t >> 5] = s;
    __syncthreads();
    float tot = red[0];
    #pragma unroll
    for (int w = 1; w < 8; w++) tot += red[w];
    const float inv = 1.0f / tot;

    for (int j = t; j < len; j += 256) row[j] *= inv;
    for (int j = len + t; j < S_; j += 256) row[j] = 0.0f;
}

// ---------------------------------------------------------------------------
// 4) O = P @ V, K-loop truncated at causal boundary (P is exactly zero beyond
//    each row's limit). Output written in [B,S,H,D] layout.
// ---------------------------------------------------------------------------
__global__ void pv_kernel()
{
    const int bh = blockIdx.z;
    const int b  = bh / H_;
    const int h  = bh % H_;
    const int Keff = (blockIdx.x + 1) * 64;   // keys j <= i0+63
    const float* A  = g_P + (size_t)bh * S_ * S_;
    const float* Bm = g_V + (size_t)bh * S_ * D_;
    float* C = g_O + (size_t)b * S_ * H_ * D_ + (size_t)h * D_;
    gemm_body<false>(A, Bm, C, Keff, S_, D_, H_ * D_, 1.0f);
}

// ---------------------------------------------------------------------------
// 5) out[B*S, D] = g_O[B*S, H*D] @ wO[H*D, D]
// ---------------------------------------------------------------------------
__global__ void out_kernel(const float* __restrict__ wO, float* __restrict__ out)
{
    gemm_body<false>(g_O, wO, out, H_ * D_, H_ * D_, D_, D_, 1.0f);
}

// ---------------------------------------------------------------------------
extern "C" void kernel_launch(void* const* d_in, const int* in_sizes, int n_in,
                              void* d_out, int out_size)
{
    const float* x  = (const float*)d_in[0];
    // d_in[1] = timestamp (dead code in reference)
    const float* wQ = (const float*)d_in[2];
    const float* wK = (const float*)d_in[3];
    const float* wV = (const float*)d_in[4];
    // const float* wV2 unused
    const float* wO = (const float*)d_in[5];
    // d_in[6] = theta (dead code)
    float* out = (float*)d_out;

    dim3 blk(256);
    proj_kernel<<<dim3(S_ / 64, D_ / 64, 3 * B_ * H_), blk>>>(x, wQ, wK, wV);
    qk_kernel<<<dim3(S_ / 64, S_ / 64, B_ * H_), blk>>>();
    softmax_kernel<<<dim3(S_, B_ * H_), blk>>>();
    pv_kernel<<<dim3(S_ / 64, D_ / 64, B_ * H_), blk>>>();
    out_kernel<<<dim3(B_ * S_ / 64, D_ / 64, 1), blk>>>(wO, out);
}

// round 2
// speedup vs baseline: 1.1399x; 1.1399x over previous
#include <cuda_runtime.h>
#include <cuda_bf16.h>

#define B_ 2
#define S_ 2048
#define D_ 256
#define H_ 8

// Scratch (no allocations allowed -> static device globals)
__device__ float g_Q[(size_t)B_ * H_ * S_ * D_];   // 32 MB
__device__ float g_K[(size_t)B_ * H_ * S_ * D_];   // 32 MB
__device__ float g_V[(size_t)B_ * H_ * S_ * D_];   // 32 MB
__device__ float g_P[(size_t)B_ * H_ * S_ * S_];   // 256 MB (scores -> probs in place)
__device__ float g_O[(size_t)B_ * S_ * H_ * D_];   // 32 MB, [B,S,H,D] for contiguous final GEMM

// ---------------------------------------------------------------------------
// 128x128 block tile fp32 GEMM, 256 threads, 8x8 micro-tile (4x float4 quads),
// BK=16, register-staged global prefetch + double-buffered smem.
// TB=false: C = A[M,K] * B[K,N]       (both row-major)
// TB=true : C = A[M,K] * B[N,K]^T     (B rows over N, K contiguous)
// M,N multiples of 128; K multiple of 16.
// ---------------------------------------------------------------------------
template <bool TB>
__device__ __forceinline__ void gemm128(const float* __restrict__ A,
                                        const float* __restrict__ Bm,
                                        float* __restrict__ C,
                                        int K, int lda, int ldb, int ldc,
                                        float scale, int mtile)
{
    __shared__ float As[2][16][128];
    __shared__ float Bs[2][16][128];

    const int t  = threadIdx.x;
    const int m0 = mtile * 128;
    const int n0 = blockIdx.y * 128;
    const int tx = t & 15;        // 0..15
    const int ty = t >> 4;        // 0..15

    // A loader: thread -> (row=t>>1, k offset=(t&1)*8), 8 floats along k
    const int arow = t >> 1;
    const int ak   = (t & 1) * 8;
    // B loader
    const int brow = TB ? (t >> 1) : (t >> 4);
    const int bcol = TB ? ((t & 1) * 8) : ((t & 15) * 8);

    const float* Aptr = A + (size_t)(m0 + arow) * lda + ak;
    const float* Bptr = TB ? (Bm + (size_t)(n0 + brow) * ldb + bcol)
                           : (Bm + (size_t)brow * ldb + (n0 + bcol));

    float4 ar0, ar1, br0, br1;

    auto load_regs = [&]() {
        ar0 = *(const float4*)(Aptr + 0);
        ar1 = *(const float4*)(Aptr + 4);
        br0 = *(const float4*)(Bptr + 0);
        br1 = *(const float4*)(Bptr + 4);
    };

    auto store_stage = [&](int buf) {
        As[buf][ak + 0][arow] = ar0.x;
        As[buf][ak + 1][arow] = ar0.y;
        As[buf][ak + 2][arow] = ar0.z;
        As[buf][ak + 3][arow] = ar0.w;
        As[buf][ak + 4][arow] = ar1.x;
        As[buf][ak + 5][arow] = ar1.y;
        As[buf][ak + 6][arow] = ar1.z;
        As[buf][ak + 7][arow] = ar1.w;
        if (TB) {
            Bs[buf][bcol + 0][brow] = br0.x;
            Bs[buf][bcol + 1][brow] = br0.y;
            Bs[buf][bcol + 2][brow] = br0.z;
            Bs[buf][bcol + 3][brow] = br0.w;
            Bs[buf][bcol + 4][brow] = br1.x;
            Bs[buf][bcol + 5][brow] = br1.y;
            Bs[buf][bcol + 6][brow] = br1.z;
            Bs[buf][bcol + 7][brow] = br1.w;
        } else {
            *(float4*)&Bs[buf][brow][bcol + 0] = br0;
            *(float4*)&Bs[buf][brow][bcol + 4] = br1;
        }
    };

    float acc[8][8] = {};

    auto compute_stage = [&](int buf) {
        #pragma unroll
        for (int kk = 0; kk < 16; kk++) {
            float4 a0 = *(const float4*)&As[buf][kk][ty * 4];
            float4 a1 = *(const float4*)&As[buf][kk][ty * 4 + 64];
            float4 b0 = *(const float4*)&Bs[buf][kk][tx * 4];
            float4 b1 = *(const float4*)&Bs[buf][kk][tx * 4 + 64];
            float av[8] = {a0.x, a0.y, a0.z, a0.w, a1.x, a1.y, a1.z, a1.w};
            float bv[8] = {b0.x, b0.y, b0.z, b0.w, b1.x, b1.y, b1.z, b1.w};
            #pragma unroll
            for (int i = 0; i < 8; i++)
                #pragma unroll
                for (int j = 0; j < 8; j++)
                    acc[i][j] += av[i] * bv[j];
        }
    };

    // Prologue
    load_regs();
    store_stage(0);
    __syncthreads();

    int buf = 0;
    for (int k0 = 16; k0 < K; k0 += 16) {
        Aptr += 16;
        Bptr += TB ? 16 : (size_t)16 * ldb;
        load_regs();              // prefetch next stage (hidden by compute)
        compute_stage(buf);
        __syncthreads();
        store_stage(buf ^ 1);
        __syncthreads();
        buf ^= 1;
    }
    compute_stage(buf);

    // Epilogue: 8 rows x 2 float4 per thread
    #pragma unroll
    for (int i = 0; i < 8; i++) {
        int row = m0 + ((i < 4) ? (ty * 4 + i) : (64 + ty * 4 + i - 4));
        float* cr = C + (size_t)row * ldc + n0;
        float4 v0 = {acc[i][0] * scale, acc[i][1] * scale,
                     acc[i][2] * scale, acc[i][3] * scale};
        float4 v1 = {acc[i][4] * scale, acc[i][5] * scale,
                     acc[i][6] * scale, acc[i][7] * scale};
        *(float4*)(cr + tx * 4)      = v0;
        *(float4*)(cr + tx * 4 + 64) = v1;
    }
}

// ---------------------------------------------------------------------------
// 1) Q/K/V projections: for each (which, b, h): [S,D] = X_b[S,D] @ W_h[D,D]
// ---------------------------------------------------------------------------
__global__ __launch_bounds__(256, 2) void proj_kernel(const float* __restrict__ x,
                                                      const float* __restrict__ wQ,
                                                      const float* __restrict__ wK,
                                                      const float* __restrict__ wV)
{
    const int z     = blockIdx.z;          // 0..3*B*H-1
    const int which = z / (B_ * H_);
    const int bh    = z % (B_ * H_);
    const int b     = bh / H_;
    const int h     = bh % H_;

    const float* A = x + (size_t)b * S_ * D_;
    const float* W = (which == 0 ? wQ : which == 1 ? wK : wV) + (size_t)h * D_ * D_;
    float* C = (which == 0 ? g_Q : which == 1 ? g_K : g_V) + (size_t)bh * S_ * D_;

    gemm128<false>(A, W, C, D_, D_, D_, D_, 1.0f, blockIdx.x);
}

// ---------------------------------------------------------------------------
// 2) Scores = Q @ K^T * (1/sqrt(D)). Skip tiles strictly above the diagonal.
// ---------------------------------------------------------------------------
__global__ __launch_bounds__(256, 2) void qk_kernel()
{
    if (blockIdx.y > blockIdx.x) return;   // fully above causal diagonal
    const int bh = blockIdx.z;
    const float* A  = g_Q + (size_t)bh * S_ * D_;
    const float* Bm = g_K + (size_t)bh * S_ * D_;
    float* C = g_P + (size_t)bh * S_ * S_;
    gemm128<true>(A, Bm, C, D_, D_, D_, S_, 0.0625f, blockIdx.x);
}

// ---------------------------------------------------------------------------
// 3) Causal softmax, one block per row; zero-fills j>i so PV is a dense GEMM.
// ---------------------------------------------------------------------------
__global__ void softmax_kernel()
{
    const int i  = blockIdx.x;
    const int bh = blockIdx.y;
    float* row = g_P + ((size_t)bh * S_ + i) * S_;
    const int len = i + 1;
    const int t = threadIdx.x;
    __shared__ float red[8];

    float m = -3.402823e38f;
    for (int j = t; j < len; j += 256) m = fmaxf(m, row[j]);
    #pragma unroll
    for (int o = 16; o; o >>= 1) m = fmaxf(m, __shfl_xor_sync(0xffffffffu, m, o));
    if ((t & 31) == 0) red[t >> 5] = m;
    __syncthreads();
    m = red[0];
    #pragma unroll
    for (int w = 1; w < 8; w++) m = fmaxf(m, red[w]);
    __syncthreads();

    float s = 0.0f;
    for (int j = t; j < len; j += 256) {
        float e = __expf(row[j] - m);
        row[j] = e;
        s += e;
    }
    #pragma unroll
    for (int o = 16; o; o >>= 1) s += __shfl_xor_sync(0xffffffffu, s, o);
    if ((t & 31) == 0) red[t >> 5] = s;
    __syncthreads();
    float tot = red[0];
    #pragma unroll
    for (int w = 1; w < 8; w++) tot += red[w];
    const float inv = 1.0f / tot;

    for (int j = t; j < len; j += 256) row[j] *= inv;
    for (int j = len + t; j < S_; j += 256) row[j] = 0.0f;
}

// ---------------------------------------------------------------------------
// 4) O = P @ V, K-loop truncated at causal boundary; heavy tiles launch first.
// ---------------------------------------------------------------------------
__global__ __launch_bounds__(256, 2) void pv_kernel()
{
    const int bh = blockIdx.z;
    const int b  = bh / H_;
    const int h  = bh % H_;
    const int mtile = gridDim.x - 1 - blockIdx.x;   // descending -> balance waves
    const int Keff = (mtile + 1) * 128;             // keys j <= m0+127
    const float* A  = g_P + (size_t)bh * S_ * S_;
    const float* Bm = g_V + (size_t)bh * S_ * D_;
    float* C = g_O + (size_t)b * S_ * H_ * D_ + (size_t)h * D_;
    gemm128<false>(A, Bm, C, Keff, S_, D_, H_ * D_, 1.0f, mtile);
}

// ---------------------------------------------------------------------------
// 5) out[B*S, D] = g_O[B*S, H*D] @ wO[H*D, D]
// ---------------------------------------------------------------------------
__global__ __launch_bounds__(256, 2) void out_kernel(const float* __restrict__ wO,
                                                     float* __restrict__ out)
{
    gemm128<false>(g_O, wO, out, H_ * D_, H_ * D_, D_, D_, 1.0f, blockIdx.x);
}

// ---------------------------------------------------------------------------
extern "C" void kernel_launch(void* const* d_in, const int* in_sizes, int n_in,
                              void* d_out, int out_size)
{
    const float* x  = (const float*)d_in[0];
    // d_in[1] = timestamp (dead code in reference)
    const float* wQ = (const float*)d_in[2];
    const float* wK = (const float*)d_in[3];
    const float* wV = (const float*)d_in[4];
    const float* wO = (const float*)d_in[5];
    // d_in[6] = theta (dead code)
    float* out = (float*)d_out;

    dim3 blk(256);
    proj_kernel<<<dim3(S_ / 128, D_ / 128, 3 * B_ * H_), blk>>>(x, wQ, wK, wV);
    qk_kernel<<<dim3(S_ / 128, S_ / 128, B_ * H_), blk>>>();
    softmax_kernel<<<dim3(S_, B_ * H_), blk>>>();
    pv_kernel<<<dim3(S_ / 128, D_ / 128, B_ * H_), blk>>>();
    out_kernel<<<dim3(B_ * S_ / 128, D_ / 128, 1), blk>>>(wO, out);
}